// round 7
// baseline (speedup 1.0000x reference)
#include <cuda_runtime.h>
#include <cuda_bf16.h>
#include <cstdint>

#define K_DIM 256
#define N_DIM 256
#define MAX_NODES 100000
#define MAX_EDGES 800000
#define SCAN_BLK 1024
#define MAX_SCAN_BLOCKS ((MAX_NODES + SCAN_BLK - 1) / SCAN_BLK)

// Static device scratch (allocation-free rule)
__device__ float g_supp[(size_t)MAX_NODES * N_DIM];
__device__ __nv_bfloat16 g_xhi[(size_t)MAX_NODES * K_DIM];
__device__ __nv_bfloat16 g_xlo[(size_t)MAX_NODES * K_DIM];
__device__ __nv_bfloat16 g_whi[K_DIM * N_DIM];
__device__ __nv_bfloat16 g_wlo[K_DIM * N_DIM];
__device__ int   g_deg[MAX_NODES];
__device__ int   g_off[MAX_NODES];
__device__ int   g_rank[MAX_EDGES];
__device__ int   g_bsum[MAX_SCAN_BLOCKS];
__device__ int   g_src_s[MAX_EDGES];
__device__ float g_w_s[MAX_EDGES];

// ---------------------------------------------------------------------------
// small helpers
// ---------------------------------------------------------------------------
__device__ __forceinline__ uint32_t smem_u32(const void* p) {
    uint32_t a;
    asm("{ .reg .u64 t; cvta.to.shared.u64 t, %1; cvt.u32.u64 %0, t; }" : "=r"(a) : "l"(p));
    return a;
}
__device__ __forceinline__ void cp16(uint32_t dst, const void* src, int sz) {
    asm volatile("cp.async.cg.shared.global [%0], [%1], 16, %2;"
                 :: "r"(dst), "l"(src), "r"(sz) : "memory");
}
#define CP_COMMIT() asm volatile("cp.async.commit_group;" ::: "memory")
#define CP_WAIT(n)  asm volatile("cp.async.wait_group %0;" :: "n"(n) : "memory")

__device__ __forceinline__ void ldm_x4(uint32_t addr, uint32_t r[4]) {
    asm volatile("ldmatrix.sync.aligned.m8n8.x4.shared.b16 {%0,%1,%2,%3}, [%4];"
                 : "=r"(r[0]), "=r"(r[1]), "=r"(r[2]), "=r"(r[3]) : "r"(addr));
}
__device__ __forceinline__ void mma_bf16(float c[4], const uint32_t a[4],
                                         uint32_t b0, uint32_t b1) {
    asm volatile(
        "mma.sync.aligned.m16n8k16.row.col.f32.bf16.bf16.f32 "
        "{%0,%1,%2,%3}, {%4,%5,%6,%7}, {%8,%9}, {%0,%1,%2,%3};"
        : "+f"(c[0]), "+f"(c[1]), "+f"(c[2]), "+f"(c[3])
        : "r"(a[0]), "r"(a[1]), "r"(a[2]), "r"(a[3]), "r"(b0), "r"(b1));
}

// ---------------------------------------------------------------------------
// Kernel 0a: convert + transpose W -> bf16 hi/lo in B-operand layout [n][k]
// ---------------------------------------------------------------------------
__global__ void convert_w_kernel(const float* __restrict__ W,
                                 __nv_bfloat16* __restrict__ whi,
                                 __nv_bfloat16* __restrict__ wlo) {
    int k = blockIdx.x;
    int n = threadIdx.x;
    float v = W[k * N_DIM + n];
    __nv_bfloat16 h = __float2bfloat16(v);
    float lo = v - __bfloat162float(h);
    whi[n * K_DIM + k] = h;
    wlo[n * K_DIM + k] = __float2bfloat16(lo);
}

// ---------------------------------------------------------------------------
// Kernel 0b: split x -> bf16 hi/lo (row-major, streaming)
// ---------------------------------------------------------------------------
__global__ void split_x_kernel(const float4* __restrict__ x4,
                               uint2* __restrict__ xhi,
                               uint2* __restrict__ xlo, int n4) {
    int idx = blockIdx.x * blockDim.x + threadIdx.x;
    if (idx >= n4) return;
    float4 v = x4[idx];
    __nv_bfloat16 h0 = __float2bfloat16(v.x);
    __nv_bfloat16 h1 = __float2bfloat16(v.y);
    __nv_bfloat16 h2 = __float2bfloat16(v.z);
    __nv_bfloat16 h3 = __float2bfloat16(v.w);
    __nv_bfloat16 l0 = __float2bfloat16(v.x - __bfloat162float(h0));
    __nv_bfloat16 l1 = __float2bfloat16(v.y - __bfloat162float(h1));
    __nv_bfloat16 l2 = __float2bfloat16(v.z - __bfloat162float(h2));
    __nv_bfloat16 l3 = __float2bfloat16(v.w - __bfloat162float(h3));
    __nv_bfloat162 hp0(h0, h1), hp1(h2, h3), lp0(l0, l1), lp1(l2, l3);
    uint2 hp, lp;
    hp.x = *reinterpret_cast<uint32_t*>(&hp0);
    hp.y = *reinterpret_cast<uint32_t*>(&hp1);
    lp.x = *reinterpret_cast<uint32_t*>(&lp0);
    lp.y = *reinterpret_cast<uint32_t*>(&lp1);
    xhi[idx] = hp;
    xlo[idx] = lp;
}

// ---------------------------------------------------------------------------
// CSR build: zero -> hist(+rank) -> scan(3) -> scatter
// ---------------------------------------------------------------------------
__global__ void zero_deg_kernel(int* __restrict__ deg, int N) {
    int i = blockIdx.x * blockDim.x + threadIdx.x;
    if (i < N) deg[i] = 0;
}
__global__ void hist_rank_kernel(const int* __restrict__ edst,
                                 int* __restrict__ deg,
                                 int* __restrict__ rank, int E) {
    int i = blockIdx.x * blockDim.x + threadIdx.x;
    if (i < E) rank[i] = atomicAdd(&deg[edst[i]], 1);
}
__global__ __launch_bounds__(SCAN_BLK) void scan1_kernel(
    const int* __restrict__ deg, int* __restrict__ off, int* __restrict__ bsum, int N) {
    __shared__ int s[SCAN_BLK];
    int tid = threadIdx.x;
    int gid = blockIdx.x * SCAN_BLK + tid;
    int v = (gid < N) ? deg[gid] : 0;
    s[tid] = v;
    __syncthreads();
#pragma unroll
    for (int d = 1; d < SCAN_BLK; d <<= 1) {
        int t = (tid >= d) ? s[tid - d] : 0;
        __syncthreads();
        s[tid] += t;
        __syncthreads();
    }
    if (gid < N) off[gid] = s[tid] - v;
    if (tid == SCAN_BLK - 1) bsum[blockIdx.x] = s[tid];
}
__global__ __launch_bounds__(SCAN_BLK) void scan2_kernel(int* __restrict__ bsum, int nb) {
    __shared__ int s[SCAN_BLK];
    int tid = threadIdx.x;
    int v = (tid < nb) ? bsum[tid] : 0;
    s[tid] = v;
    __syncthreads();
#pragma unroll
    for (int d = 1; d < SCAN_BLK; d <<= 1) {
        int t = (tid >= d) ? s[tid - d] : 0;
        __syncthreads();
        s[tid] += t;
        __syncthreads();
    }
    if (tid < nb) bsum[tid] = s[tid] - v;
}
__global__ void scan3_kernel(int* __restrict__ off, const int* __restrict__ bsum, int N) {
    int gid = blockIdx.x * blockDim.x + threadIdx.x;
    if (gid < N) off[gid] += bsum[gid / SCAN_BLK];
}
__global__ void scatter_kernel(const int* __restrict__ esrc,
                               const int* __restrict__ edst,
                               const float* __restrict__ ew,
                               const int* __restrict__ off,
                               const int* __restrict__ rank,
                               int* __restrict__ src_s,
                               float* __restrict__ w_s, int E) {
    int e = blockIdx.x * blockDim.x + threadIdx.x;
    if (e < E) {
        int pos = off[edst[e]] + rank[e];
        src_s[pos] = esrc[e];
        w_s[pos] = ew[e];
    }
}

// ---------------------------------------------------------------------------
// Aggregate: one warp per dst node (R4 form — at L2 gather floor)
// ---------------------------------------------------------------------------
__global__ __launch_bounds__(256) void agg_kernel(
    const float* __restrict__ supp,
    const int* __restrict__ src_s,
    const float* __restrict__ w_s,
    const int* __restrict__ off,
    const float* __restrict__ bias,
    float* __restrict__ out,
    int N, int E) {

    const int warp = (blockIdx.x * blockDim.x + threadIdx.x) >> 5;
    const int lane = threadIdx.x & 31;
    if (warp >= N) return;

    const int beg = off[warp];
    const int end = (warp + 1 < N) ? off[warp + 1] : E;

    const float4* bias4 = reinterpret_cast<const float4*>(bias);
    float4 acc0 = bias4[lane * 2];
    float4 acc1 = bias4[lane * 2 + 1];

    for (int j = beg; j < end; ++j) {
        const int src = __ldg(&src_s[j]);
        const float w = __ldg(&w_s[j]);
        const float4* srow = reinterpret_cast<const float4*>(supp + (size_t)src * N_DIM);
        float4 a = __ldg(&srow[lane * 2]);
        float4 b = __ldg(&srow[lane * 2 + 1]);
        acc0.x = fmaf(a.x, w, acc0.x); acc0.y = fmaf(a.y, w, acc0.y);
        acc0.z = fmaf(a.z, w, acc0.z); acc0.w = fmaf(a.w, w, acc0.w);
        acc1.x = fmaf(b.x, w, acc1.x); acc1.y = fmaf(b.y, w, acc1.y);
        acc1.z = fmaf(b.z, w, acc1.z); acc1.w = fmaf(b.w, w, acc1.w);
    }

    float4* drow = reinterpret_cast<float4*>(out + (size_t)warp * N_DIM);
    drow[lane * 2] = acc0;
    drow[lane * 2 + 1] = acc1;
}

// ---------------------------------------------------------------------------
// GEMM: cp.async 3-stage pipeline, BM=128, BN=256 (full), BK=32, 8 warps.
// supp[M,256] = xhi@Whi + xhi@Wlo + xlo@Whi  (fp32 accum)
// smem rows: 64B data + 16B pad (stride 80) -> conflict-free LDSM, 16B-aligned cp.
// ---------------------------------------------------------------------------
#define BK2 32
#define ROWB 80
#define A_T (128 * ROWB)              /* 10240 */
#define B_T (256 * ROWB)              /* 20480 */
#define O_AHI 0
#define O_ALO (A_T)
#define O_BHI (2 * A_T)
#define O_BLO (2 * A_T + B_T)
#define STG (2 * A_T + 2 * B_T)       /* 61440 */
#define GEMM_SMEM (3 * STG)           /* 184320 */

__global__ __launch_bounds__(256, 1) void gemm_cp_kernel(
    const __nv_bfloat16* __restrict__ xhi,
    const __nv_bfloat16* __restrict__ xlo,
    const __nv_bfloat16* __restrict__ whi,
    const __nv_bfloat16* __restrict__ wlo,
    float* __restrict__ supp, int M) {

    extern __shared__ __align__(128) char smem[];
    const uint32_t sbase = smem_u32(smem);

    const int tid = threadIdx.x;
    const int wid = tid >> 5;
    const int lane = tid & 31;
    const int rowBase = blockIdx.x * 128;

    const int warp_m = (wid >> 2) * 64;   // 0 or 64
    const int warp_n = (wid & 3) * 64;    // 0,64,128,192

    // ldmatrix lane addressing (same mapping as validated R3 kernel)
    const int a_lr = lane & 15;
    const int a_lk = (lane >> 4) * 8;
    const int b_ln = ((lane >> 4) * 8) + (lane & 7);
    const int b_lk = ((lane >> 3) & 1) * 8;

    float acc[4][8][4];
#pragma unroll
    for (int i = 0; i < 4; i++)
#pragma unroll
        for (int j = 0; j < 8; j++)
#pragma unroll
            for (int q = 0; q < 4; q++) acc[i][j][q] = 0.0f;

    // stage issue: A (hi/lo) 512 16B-chunks each, B (hi/lo) 1024 each
    auto issue = [&](int s, int c) {
        const int k0 = c * BK2;
        const uint32_t st = sbase + s * STG;
#pragma unroll
        for (int i = 0; i < 2; i++) {
            int a = tid + i * 256;
            int row = a >> 2, cc = a & 3;
            int grow = rowBase + row;
            int ok = (grow < M);
            int crow = ok ? grow : 0;
            int sz = ok ? 16 : 0;
            const __nv_bfloat16* sh = xhi + (size_t)crow * K_DIM + k0 + cc * 8;
            const __nv_bfloat16* sl = xlo + (size_t)crow * K_DIM + k0 + cc * 8;
            cp16(st + O_AHI + row * ROWB + cc * 16, sh, sz);
            cp16(st + O_ALO + row * ROWB + cc * 16, sl, sz);
        }
#pragma unroll
        for (int i = 0; i < 4; i++) {
            int a = tid + i * 256;
            int row = a >> 2, cc = a & 3;
            const __nv_bfloat16* sh = whi + (size_t)row * K_DIM + k0 + cc * 8;
            const __nv_bfloat16* sl = wlo + (size_t)row * K_DIM + k0 + cc * 8;
            cp16(st + O_BHI + row * ROWB + cc * 16, sh, 16);
            cp16(st + O_BLO + row * ROWB + cc * 16, sl, 16);
        }
        CP_COMMIT();
    };

    auto compute = [&](int s) {
        const uint32_t st = sbase + s * STG;
#pragma unroll
        for (int ks = 0; ks < 2; ks++) {
            uint32_t ah[4][4], al[4][4];
#pragma unroll
            for (int mi = 0; mi < 4; mi++) {
                uint32_t off = (uint32_t)(warp_m + mi * 16 + a_lr) * ROWB +
                               (ks * 16 + a_lk) * 2;
                ldm_x4(st + O_AHI + off, ah[mi]);
                ldm_x4(st + O_ALO + off, al[mi]);
            }
#pragma unroll
            for (int nj = 0; nj < 4; nj++) {
                uint32_t off = (uint32_t)(warp_n + nj * 16 + b_ln) * ROWB +
                               (ks * 16 + b_lk) * 2;
                uint32_t bh[4], bl[4];
                ldm_x4(st + O_BHI + off, bh);
                ldm_x4(st + O_BLO + off, bl);
#pragma unroll
                for (int mi = 0; mi < 4; mi++) {
                    mma_bf16(acc[mi][nj * 2 + 0], ah[mi], bh[0], bh[1]);
                    mma_bf16(acc[mi][nj * 2 + 0], ah[mi], bl[0], bl[1]);
                    mma_bf16(acc[mi][nj * 2 + 0], al[mi], bh[0], bh[1]);
                    mma_bf16(acc[mi][nj * 2 + 1], ah[mi], bh[2], bh[3]);
                    mma_bf16(acc[mi][nj * 2 + 1], ah[mi], bl[2], bl[3]);
                    mma_bf16(acc[mi][nj * 2 + 1], al[mi], bh[2], bh[3]);
                }
            }
        }
    };

    // prologue: 2 stages in flight
    issue(0, 0);
    issue(1, 1);

#pragma unroll 1
    for (int c = 0; c < K_DIM / BK2; ++c) {
        CP_WAIT(1);            // chunk c's group complete
        __syncthreads();
        if (c + 2 < K_DIM / BK2) issue((c + 2) % 3, c + 2);
        compute(c % 3);
        __syncthreads();       // all warps done with buf c%3 before rewrite next iter
    }

    // epilogue
    const int lrow = lane >> 2;
    const int lcol = (lane & 3) * 2;
#pragma unroll
    for (int mi = 0; mi < 4; mi++) {
#pragma unroll
        for (int half = 0; half < 2; half++) {
            int grow = rowBase + warp_m + mi * 16 + lrow + half * 8;
            if (grow < M) {
                float* dst = supp + (size_t)grow * N_DIM + warp_n;
#pragma unroll
                for (int ni = 0; ni < 8; ni++) {
                    float2 v = half ? make_float2(acc[mi][ni][2], acc[mi][ni][3])
                                    : make_float2(acc[mi][ni][0], acc[mi][ni][1]);
                    *reinterpret_cast<float2*>(dst + ni * 8 + lcol) = v;
                }
            }
        }
    }
}

// ---------------------------------------------------------------------------
// Launch — CSR build on a forked side stream, overlapped with split+GEMM.
// ---------------------------------------------------------------------------
extern "C" void kernel_launch(void* const* d_in, const int* in_sizes, int n_in,
                              void* d_out, int out_size) {
    const float* x      = (const float*)d_in[0];
    const float* weight = (const float*)d_in[1];
    const float* bias   = (const float*)d_in[2];
    const float* ew     = (const float*)d_in[3];
    const int*   esrc   = (const int*)d_in[4];
    const int*   edst   = (const int*)d_in[5];
    float* out = (float*)d_out;

    const int M = in_sizes[0] / K_DIM;   // 100000
    const int E = in_sizes[3];           // 800000

    float* supp;          cudaGetSymbolAddress((void**)&supp, g_supp);
    __nv_bfloat16* xhi;   cudaGetSymbolAddress((void**)&xhi, g_xhi);
    __nv_bfloat16* xlo;   cudaGetSymbolAddress((void**)&xlo, g_xlo);
    __nv_bfloat16* whi;   cudaGetSymbolAddress((void**)&whi, g_whi);
    __nv_bfloat16* wlo;   cudaGetSymbolAddress((void**)&wlo, g_wlo);
    int* deg;             cudaGetSymbolAddress((void**)&deg, g_deg);
    int* off;             cudaGetSymbolAddress((void**)&off, g_off);
    int* rank;            cudaGetSymbolAddress((void**)&rank, g_rank);
    int* bsum;            cudaGetSymbolAddress((void**)&bsum, g_bsum);
    int* src_s;           cudaGetSymbolAddress((void**)&src_s, g_src_s);
    float* w_s;           cudaGetSymbolAddress((void**)&w_s, g_w_s);

    static cudaStream_t s_side = nullptr;
    static cudaEvent_t  s_fork = nullptr, s_join = nullptr;
    static bool s_init = false;
    if (!s_init) {
        cudaFuncSetAttribute(gemm_cp_kernel,
                             cudaFuncAttributeMaxDynamicSharedMemorySize, GEMM_SMEM);
        cudaStreamCreateWithFlags(&s_side, cudaStreamNonBlocking);
        cudaEventCreateWithFlags(&s_fork, cudaEventDisableTiming);
        cudaEventCreateWithFlags(&s_join, cudaEventDisableTiming);
        s_init = true;
    }

    const int nblk_scan = (M + SCAN_BLK - 1) / SCAN_BLK;

    // Fork
    cudaEventRecord(s_fork, 0);
    cudaStreamWaitEvent(s_side, s_fork, 0);

    // side stream: CSR build
    zero_deg_kernel<<<(M + 255) / 256, 256, 0, s_side>>>(deg, M);
    hist_rank_kernel<<<(E + 255) / 256, 256, 0, s_side>>>(edst, deg, rank, E);
    scan1_kernel<<<nblk_scan, SCAN_BLK, 0, s_side>>>(deg, off, bsum, M);
    scan2_kernel<<<1, SCAN_BLK, 0, s_side>>>(bsum, nblk_scan);
    scan3_kernel<<<(M + 255) / 256, 256, 0, s_side>>>(off, bsum, M);
    scatter_kernel<<<(E + 255) / 256, 256, 0, s_side>>>(esrc, edst, ew, off, rank,
                                                        src_s, w_s, E);
    cudaEventRecord(s_join, s_side);

    // main stream: convert W, split x, GEMM
    convert_w_kernel<<<K_DIM, N_DIM>>>(weight, whi, wlo);
    {
        int n4 = M * (K_DIM / 4);
        split_x_kernel<<<(n4 + 255) / 256, 256>>>(
            (const float4*)x, (uint2*)xhi, (uint2*)xlo, n4);
    }
    {
        int grid = (M + 127) / 128;
        gemm_cp_kernel<<<grid, 256, GEMM_SMEM>>>(xhi, xlo, whi, wlo, supp, M);
    }

    // Join, then aggregate
    cudaStreamWaitEvent(0, s_join, 0);
    {
        int blocks = (M + 7) / 8;
        agg_kernel<<<blocks, 256>>>(supp, src_s, w_s, off, bias, out, M, E);
    }
}

// round 8
// speedup vs baseline: 1.1380x; 1.1380x over previous
#include <cuda_runtime.h>
#include <cuda_bf16.h>
#include <cstdint>

#define K_DIM 256
#define N_DIM 256
#define MAX_NODES 100000
#define MAX_EDGES 800000
#define SCAN_BLK 1024
#define MAX_SCAN_BLOCKS ((MAX_NODES + SCAN_BLK - 1) / SCAN_BLK)

// Static device scratch (allocation-free rule)
__device__ float g_supp[(size_t)MAX_NODES * N_DIM];
__device__ __nv_bfloat16 g_whi[K_DIM * N_DIM];
__device__ __nv_bfloat16 g_wlo[K_DIM * N_DIM];
__device__ int   g_deg[MAX_NODES];
__device__ int   g_off[MAX_NODES];
__device__ int   g_rank[MAX_EDGES];
__device__ int   g_bsum[MAX_SCAN_BLOCKS];
__device__ int   g_src_s[MAX_EDGES];
__device__ float g_w_s[MAX_EDGES];

// ---------------------------------------------------------------------------
// helpers
// ---------------------------------------------------------------------------
__device__ __forceinline__ uint32_t smem_u32(const void* p) {
    uint32_t a;
    asm("{ .reg .u64 t; cvta.to.shared.u64 t, %1; cvt.u32.u64 %0, t; }" : "=r"(a) : "l"(p));
    return a;
}
__device__ __forceinline__ void cp16(uint32_t dst, const void* src) {
    asm volatile("cp.async.cg.shared.global [%0], [%1], 16;"
                 :: "r"(dst), "l"(src) : "memory");
}
#define CP_COMMIT() asm volatile("cp.async.commit_group;" ::: "memory")
#define CP_WAIT(n)  asm volatile("cp.async.wait_group %0;" :: "n"(n) : "memory")

__device__ __forceinline__ void ldm_x4(uint32_t addr, uint32_t r[4]) {
    asm volatile("ldmatrix.sync.aligned.m8n8.x4.shared.b16 {%0,%1,%2,%3}, [%4];"
                 : "=r"(r[0]), "=r"(r[1]), "=r"(r[2]), "=r"(r[3]) : "r"(addr));
}
__device__ __forceinline__ void mma_bf16(float c[4], const uint32_t a[4],
                                         uint32_t b0, uint32_t b1) {
    asm volatile(
        "mma.sync.aligned.m16n8k16.row.col.f32.bf16.bf16.f32 "
        "{%0,%1,%2,%3}, {%4,%5,%6,%7}, {%8,%9}, {%0,%1,%2,%3};"
        : "+f"(c[0]), "+f"(c[1]), "+f"(c[2]), "+f"(c[3])
        : "r"(a[0]), "r"(a[1]), "r"(a[2]), "r"(a[3]), "r"(b0), "r"(b1));
}
__device__ __forceinline__ void split2(float x, float y, uint32_t& hp, uint32_t& lp) {
    __nv_bfloat16 hx = __float2bfloat16(x);
    __nv_bfloat16 hy = __float2bfloat16(y);
    __nv_bfloat16 lx = __float2bfloat16(x - __bfloat162float(hx));
    __nv_bfloat16 ly = __float2bfloat16(y - __bfloat162float(hy));
    __nv_bfloat162 h2(hx, hy), l2(lx, ly);
    hp = *reinterpret_cast<uint32_t*>(&h2);
    lp = *reinterpret_cast<uint32_t*>(&l2);
}

// ---------------------------------------------------------------------------
// Kernel 0: convert + transpose W -> bf16 hi/lo, B-operand layout [n][k]
// ---------------------------------------------------------------------------
__global__ void convert_w_kernel(const float* __restrict__ W,
                                 __nv_bfloat16* __restrict__ whi,
                                 __nv_bfloat16* __restrict__ wlo) {
    int k = blockIdx.x;
    int n = threadIdx.x;
    float v = W[k * N_DIM + n];
    __nv_bfloat16 h = __float2bfloat16(v);
    float lo = v - __bfloat162float(h);
    whi[n * K_DIM + k] = h;
    wlo[n * K_DIM + k] = __float2bfloat16(lo);
}

// ---------------------------------------------------------------------------
// CSR build: zero -> hist(+rank) -> scan(3) -> scatter
// ---------------------------------------------------------------------------
__global__ void zero_deg_kernel(int* __restrict__ deg, int N) {
    int i = blockIdx.x * blockDim.x + threadIdx.x;
    if (i < N) deg[i] = 0;
}
__global__ void hist_rank_kernel(const int* __restrict__ edst,
                                 int* __restrict__ deg,
                                 int* __restrict__ rank, int E) {
    int i = blockIdx.x * blockDim.x + threadIdx.x;
    if (i < E) rank[i] = atomicAdd(&deg[edst[i]], 1);
}
__global__ __launch_bounds__(SCAN_BLK) void scan1_kernel(
    const int* __restrict__ deg, int* __restrict__ off, int* __restrict__ bsum, int N) {
    __shared__ int s[SCAN_BLK];
    int tid = threadIdx.x;
    int gid = blockIdx.x * SCAN_BLK + tid;
    int v = (gid < N) ? deg[gid] : 0;
    s[tid] = v;
    __syncthreads();
#pragma unroll
    for (int d = 1; d < SCAN_BLK; d <<= 1) {
        int t = (tid >= d) ? s[tid - d] : 0;
        __syncthreads();
        s[tid] += t;
        __syncthreads();
    }
    if (gid < N) off[gid] = s[tid] - v;
    if (tid == SCAN_BLK - 1) bsum[blockIdx.x] = s[tid];
}
__global__ __launch_bounds__(SCAN_BLK) void scan2_kernel(int* __restrict__ bsum, int nb) {
    __shared__ int s[SCAN_BLK];
    int tid = threadIdx.x;
    int v = (tid < nb) ? bsum[tid] : 0;
    s[tid] = v;
    __syncthreads();
#pragma unroll
    for (int d = 1; d < SCAN_BLK; d <<= 1) {
        int t = (tid >= d) ? s[tid - d] : 0;
        __syncthreads();
        s[tid] += t;
        __syncthreads();
    }
    if (tid < nb) bsum[tid] = s[tid] - v;
}
__global__ void scan3_kernel(int* __restrict__ off, const int* __restrict__ bsum, int N) {
    int gid = blockIdx.x * blockDim.x + threadIdx.x;
    if (gid < N) off[gid] += bsum[gid / SCAN_BLK];
}
__global__ void scatter_kernel(const int* __restrict__ esrc,
                               const int* __restrict__ edst,
                               const float* __restrict__ ew,
                               const int* __restrict__ off,
                               const int* __restrict__ rank,
                               int* __restrict__ src_s,
                               float* __restrict__ w_s, int E) {
    int e = blockIdx.x * blockDim.x + threadIdx.x;
    if (e < E) {
        int pos = off[edst[e]] + rank[e];
        src_s[pos] = esrc[e];
        w_s[pos] = ew[e];
    }
}

// ---------------------------------------------------------------------------
// Aggregate: one warp per dst node (at L2 gather floor — do not touch)
// ---------------------------------------------------------------------------
__global__ __launch_bounds__(256) void agg_kernel(
    const float* __restrict__ supp,
    const int* __restrict__ src_s,
    const float* __restrict__ w_s,
    const int* __restrict__ off,
    const float* __restrict__ bias,
    float* __restrict__ out,
    int N, int E) {

    const int warp = (blockIdx.x * blockDim.x + threadIdx.x) >> 5;
    const int lane = threadIdx.x & 31;
    if (warp >= N) return;

    const int beg = off[warp];
    const int end = (warp + 1 < N) ? off[warp + 1] : E;

    const float4* bias4 = reinterpret_cast<const float4*>(bias);
    float4 acc0 = bias4[lane * 2];
    float4 acc1 = bias4[lane * 2 + 1];

    for (int j = beg; j < end; ++j) {
        const int src = __ldg(&src_s[j]);
        const float w = __ldg(&w_s[j]);
        const float4* srow = reinterpret_cast<const float4*>(supp + (size_t)src * N_DIM);
        float4 a = __ldg(&srow[lane * 2]);
        float4 b = __ldg(&srow[lane * 2 + 1]);
        acc0.x = fmaf(a.x, w, acc0.x); acc0.y = fmaf(a.y, w, acc0.y);
        acc0.z = fmaf(a.z, w, acc0.z); acc0.w = fmaf(a.w, w, acc0.w);
        acc1.x = fmaf(b.x, w, acc1.x); acc1.y = fmaf(b.y, w, acc1.y);
        acc1.z = fmaf(b.z, w, acc1.z); acc1.w = fmaf(b.w, w, acc1.w);
    }

    float4* drow = reinterpret_cast<float4*>(out + (size_t)warp * N_DIM);
    drow[lane * 2] = acc0;
    drow[lane * 2 + 1] = acc1;
}

// ---------------------------------------------------------------------------
// GEMM: BM=128, BN=128, BK=32, 2-stage, occupancy 2.
// A: reg-staged f32 -> hi/lo split -> STS.  B: cp.async (bf16 already).
// smem rows stride 80B (64B data + 16B pad): conflict-free LDSM.
// ---------------------------------------------------------------------------
#define BK2 32
#define ROWB 80
#define T128 (128 * ROWB)             /* 10240 per tile */
#define O_AHI 0
#define O_ALO (T128)
#define O_BHI (2 * T128)
#define O_BLO (3 * T128)
#define STG (4 * T128)                /* 40960 */
#define GEMM_SMEM (2 * STG)           /* 81920 -> 2 CTAs/SM */

__global__ __launch_bounds__(256, 2) void gemm_occ2_kernel(
    const float* __restrict__ x,
    const __nv_bfloat16* __restrict__ whi,
    const __nv_bfloat16* __restrict__ wlo,
    float* __restrict__ supp, int M) {

    extern __shared__ __align__(128) char smem[];
    const uint32_t sbase = smem_u32(smem);

    const int tid = threadIdx.x;
    const int wid = tid >> 5;
    const int lane = tid & 31;
    const int rowBase = blockIdx.y * 128;
    const int colBase = blockIdx.x * 128;

    const int warp_m = (wid >> 2) * 64;   // 0 or 64
    const int warp_n = (wid & 3) * 32;    // 0,32,64,96

    // A gmem->reg mapping: row = tid>>1 (0..127), khalf = (tid&1)*16
    const int ld_row = tid >> 1;
    const int ld_kc  = (tid & 1) * 16;
    const int a_grow = rowBase + ld_row;
    const bool a_ok = (a_grow < M);
    const float4* x4 = reinterpret_cast<const float4*>(x);

    // B cp.async mapping: 128 rows x 4 16B-chunks = 512 per tile; 2 iters
    // ldmatrix lane addressing (validated mapping)
    const int a_lr = lane & 15;
    const int a_lk = (lane >> 4) * 8;
    const int b_ln = ((lane >> 4) * 8) + (lane & 7);
    const int b_lk = ((lane >> 3) & 1) * 8;

    float acc[4][4][4];
#pragma unroll
    for (int i = 0; i < 4; i++)
#pragma unroll
        for (int j = 0; j < 4; j++)
#pragma unroll
            for (int q = 0; q < 4; q++) acc[i][j][q] = 0.0f;

    float4 ga[4];

    auto load_A = [&](int c) {
        const int k0 = c * BK2;
#pragma unroll
        for (int j = 0; j < 4; j++) {
            ga[j] = a_ok ? x4[(size_t)a_grow * (K_DIM / 4) + ((k0 + ld_kc) >> 2) + j]
                         : make_float4(0.f, 0.f, 0.f, 0.f);
        }
    };
    auto store_A = [&](int s) {
        const uint32_t st = sbase + s * STG;
        uint32_t a_off = (uint32_t)ld_row * ROWB + ld_kc * 2;
#pragma unroll
        for (int j = 0; j < 4; j++) {
            uint32_t hp0, lp0, hp1, lp1;
            split2(ga[j].x, ga[j].y, hp0, lp0);
            split2(ga[j].z, ga[j].w, hp1, lp1);
            asm volatile("st.shared.v2.b32 [%0], {%1, %2};"
                         :: "r"(st + O_AHI + a_off + j * 8), "r"(hp0), "r"(hp1) : "memory");
            asm volatile("st.shared.v2.b32 [%0], {%1, %2};"
                         :: "r"(st + O_ALO + a_off + j * 8), "r"(lp0), "r"(lp1) : "memory");
        }
    };
    auto issue_B = [&](int s, int c) {
        const int k0 = c * BK2;
        const uint32_t st = sbase + s * STG;
#pragma unroll
        for (int i = 0; i < 2; i++) {
            int a = tid + i * 256;
            int row = a >> 2, cc = a & 3;     // row 0..127, 16B chunk 0..3
            const __nv_bfloat16* sh = whi + (size_t)(colBase + row) * K_DIM + k0 + cc * 8;
            const __nv_bfloat16* sl = wlo + (size_t)(colBase + row) * K_DIM + k0 + cc * 8;
            cp16(st + O_BHI + row * ROWB + cc * 16, sh);
            cp16(st + O_BLO + row * ROWB + cc * 16, sl);
        }
        CP_COMMIT();
    };

    auto compute = [&](int s) {
        const uint32_t st = sbase + s * STG;
#pragma unroll
        for (int ks = 0; ks < 2; ks++) {
            uint32_t ah[4][4], al[4][4];
#pragma unroll
            for (int mi = 0; mi < 4; mi++) {
                uint32_t off = (uint32_t)(warp_m + mi * 16 + a_lr) * ROWB +
                               (ks * 16 + a_lk) * 2;
                ldm_x4(st + O_AHI + off, ah[mi]);
                ldm_x4(st + O_ALO + off, al[mi]);
            }
#pragma unroll
            for (int pi = 0; pi < 2; pi++) {
                uint32_t off = (uint32_t)(warp_n + pi * 16 + b_ln) * ROWB +
                               (ks * 16 + b_lk) * 2;
                uint32_t bh[4], bl[4];
                ldm_x4(st + O_BHI + off, bh);
                ldm_x4(st + O_BLO + off, bl);
#pragma unroll
                for (int mi = 0; mi < 4; mi++) {
                    mma_bf16(acc[mi][pi * 2 + 0], ah[mi], bh[0], bh[1]);
                    mma_bf16(acc[mi][pi * 2 + 0], ah[mi], bl[0], bl[1]);
                    mma_bf16(acc[mi][pi * 2 + 0], al[mi], bh[0], bh[1]);
                    mma_bf16(acc[mi][pi * 2 + 1], ah[mi], bh[2], bh[3]);
                    mma_bf16(acc[mi][pi * 2 + 1], ah[mi], bl[2], bl[3]);
                    mma_bf16(acc[mi][pi * 2 + 1], al[mi], bh[2], bh[3]);
                }
            }
        }
    };

    // prologue
    load_A(0);
    store_A(0);
    issue_B(0, 0);

#pragma unroll 1
    for (int c = 0; c < K_DIM / BK2; ++c) {
        const bool more = (c + 1 < K_DIM / BK2);
        if (more) {
            load_A(c + 1);                    // LDG early, consumed at step 6
            issue_B((c + 1) & 1, c + 1);      // buffer (c+1)&1 free: compute(c-1) done
        }
        if (more) { CP_WAIT(1); } else { CP_WAIT(0); }
        __syncthreads();                       // B(c) + A(c) visible to all
        compute(c & 1);
        __syncthreads();                       // release buffer c&1
        if (more) store_A((c + 1) & 1);
    }

    // epilogue
    const int lrow = lane >> 2;
    const int lcol = (lane & 3) * 2;
#pragma unroll
    for (int mi = 0; mi < 4; mi++) {
#pragma unroll
        for (int half = 0; half < 2; half++) {
            int grow = rowBase + warp_m + mi * 16 + lrow + half * 8;
            if (grow < M) {
                float* dst = supp + (size_t)grow * N_DIM + colBase + warp_n;
#pragma unroll
                for (int ni = 0; ni < 4; ni++) {
                    float2 v = half ? make_float2(acc[mi][ni][2], acc[mi][ni][3])
                                    : make_float2(acc[mi][ni][0], acc[mi][ni][1]);
                    *reinterpret_cast<float2*>(dst + ni * 8 + lcol) = v;
                }
            }
        }
    }
}

// ---------------------------------------------------------------------------
// Launch — CSR build forked on side stream, overlapped with convert+GEMM.
// ---------------------------------------------------------------------------
extern "C" void kernel_launch(void* const* d_in, const int* in_sizes, int n_in,
                              void* d_out, int out_size) {
    const float* x      = (const float*)d_in[0];
    const float* weight = (const float*)d_in[1];
    const float* bias   = (const float*)d_in[2];
    const float* ew     = (const float*)d_in[3];
    const int*   esrc   = (const int*)d_in[4];
    const int*   edst   = (const int*)d_in[5];
    float* out = (float*)d_out;

    const int M = in_sizes[0] / K_DIM;   // 100000
    const int E = in_sizes[3];           // 800000

    float* supp;          cudaGetSymbolAddress((void**)&supp, g_supp);
    __nv_bfloat16* whi;   cudaGetSymbolAddress((void**)&whi, g_whi);
    __nv_bfloat16* wlo;   cudaGetSymbolAddress((void**)&wlo, g_wlo);
    int* deg;             cudaGetSymbolAddress((void**)&deg, g_deg);
    int* off;             cudaGetSymbolAddress((void**)&off, g_off);
    int* rank;            cudaGetSymbolAddress((void**)&rank, g_rank);
    int* bsum;            cudaGetSymbolAddress((void**)&bsum, g_bsum);
    int* src_s;           cudaGetSymbolAddress((void**)&src_s, g_src_s);
    float* w_s;           cudaGetSymbolAddress((void**)&w_s, g_w_s);

    static cudaStream_t s_side = nullptr;
    static cudaEvent_t  s_fork = nullptr, s_join = nullptr;
    static bool s_init = false;
    if (!s_init) {
        cudaFuncSetAttribute(gemm_occ2_kernel,
                             cudaFuncAttributeMaxDynamicSharedMemorySize, GEMM_SMEM);
        cudaStreamCreateWithFlags(&s_side, cudaStreamNonBlocking);
        cudaEventCreateWithFlags(&s_fork, cudaEventDisableTiming);
        cudaEventCreateWithFlags(&s_join, cudaEventDisableTiming);
        s_init = true;
    }

    const int nblk_scan = (M + SCAN_BLK - 1) / SCAN_BLK;

    // Fork
    cudaEventRecord(s_fork, 0);
    cudaStreamWaitEvent(s_side, s_fork, 0);

    // side stream: CSR build
    zero_deg_kernel<<<(M + 255) / 256, 256, 0, s_side>>>(deg, M);
    hist_rank_kernel<<<(E + 255) / 256, 256, 0, s_side>>>(edst, deg, rank, E);
    scan1_kernel<<<nblk_scan, SCAN_BLK, 0, s_side>>>(deg, off, bsum, M);
    scan2_kernel<<<1, SCAN_BLK, 0, s_side>>>(bsum, nblk_scan);
    scan3_kernel<<<(M + 255) / 256, 256, 0, s_side>>>(off, bsum, M);
    scatter_kernel<<<(E + 255) / 256, 256, 0, s_side>>>(esrc, edst, ew, off, rank,
                                                        src_s, w_s, E);
    cudaEventRecord(s_join, s_side);

    // main stream: convert W, GEMM
    convert_w_kernel<<<K_DIM, N_DIM>>>(weight, whi, wlo);
    {
        dim3 grid(N_DIM / 128, (M + 127) / 128);
        gemm_occ2_kernel<<<grid, 256, GEMM_SMEM>>>(x, whi, wlo, supp, M);
    }

    // Join, then aggregate
    cudaStreamWaitEvent(0, s_join, 0);
    {
        int blocks = (M + 7) / 8;
        agg_kernel<<<blocks, 256>>>(supp, src_s, w_s, off, bias, out, M, E);
    }
}